// round 2
// baseline (speedup 1.0000x reference)
#include <cuda_runtime.h>
#include <cuda_bf16.h>

// SmallVDSR: 20-layer 3x3 conv stack on [8,1,512,512] fp32.
//   conv1: 1->8 + relu
//   conv2..19: 18x (8->8 + relu), weights stacked in wmid [18,8,8,3,3]
//   conv20: 8->1, no relu
//
// Layer-wise ping-pong through two 64MB __device__ activation buffers.
// Each block computes a 32x32 output tile for ALL output channels:
//   blockDim (32,8), each thread owns 4 output rows x OC channels in regs.
//   Input tile (IC x 34 x 34) + repacked weights staged in SMEM.

#define H 512
#define W 512
#define NB 8
#define CH 8
#define PLANE (H * W)          // 262144 = 1<<18

__device__ float g_bufA[NB * CH * PLANE];
__device__ float g_bufB[NB * CH * PLANE];

template <int IC, int OC, bool RELU>
__global__ void __launch_bounds__(256, 4)
conv3x3_kernel(const float* __restrict__ in,
               const float* __restrict__ wg,
               float* __restrict__ out)
{
    constexpr int TX = 32;          // tile width
    constexpr int TY = 32;          // tile height
    constexpr int RY = 4;           // rows per thread
    constexpr int SW = TX + 2;      // 34: smem tile row width
    constexpr int SH = TY + 2;      // 34
    constexpr int STILE = SW * SH;  // 1156

    __shared__ float s_in[IC * STILE];
    __shared__ float s_w[IC * 9 * OC];   // layout [ic][ky*3+kx][oc] (oc contiguous)

    const int tx = threadIdx.x;          // 0..31
    const int ty = threadIdx.y;          // 0..7
    const int tid = ty * 32 + tx;
    const int n = blockIdx.z;
    const int gx0 = blockIdx.x * TX;
    const int gy0 = blockIdx.y * TY;

    const float* inb = in + (size_t)n * IC * PLANE;

    // ---- stage input tile (with 1-pixel zero halo) ----
    #pragma unroll 1
    for (int idx = tid; idx < IC * STILE; idx += 256) {
        int ic = idx / STILE;
        int r  = idx - ic * STILE;
        int sy = r / SW;
        int sx = r - sy * SW;
        int gy = gy0 + sy - 1;
        int gx = gx0 + sx - 1;
        float v = 0.0f;
        if (gy >= 0 && gy < H && gx >= 0 && gx < W)
            v = inb[ic * PLANE + (gy << 9) + gx];
        s_in[idx] = v;
    }

    // ---- stage + repack weights: global [oc][ic][ky][kx] -> smem [ic][k][oc] ----
    #pragma unroll 1
    for (int idx = tid; idx < IC * 9 * OC; idx += 256) {
        int oc = idx % OC;
        int t  = idx / OC;
        int ic = t / 9;
        int k  = t - ic * 9;
        s_w[idx] = wg[(oc * IC + ic) * 9 + k];
    }

    __syncthreads();

    float acc[RY][OC];
    #pragma unroll
    for (int ry = 0; ry < RY; ++ry)
        #pragma unroll
        for (int oc = 0; oc < OC; ++oc)
            acc[ry][oc] = 0.0f;

    const int y0 = ty * RY;   // local output row base for this thread

    #pragma unroll 1
    for (int ic = 0; ic < IC; ++ic) {
        const float* si = &s_in[ic * STILE];
        const float* sw = &s_w[ic * 9 * OC];
        #pragma unroll
        for (int ky = 0; ky < 3; ++ky) {
            #pragma unroll
            for (int kx = 0; kx < 3; ++kx) {
                float wv[OC];
                #pragma unroll
                for (int oc = 0; oc < OC; ++oc)
                    wv[oc] = sw[(ky * 3 + kx) * OC + oc];
                #pragma unroll
                for (int ry = 0; ry < RY; ++ry) {
                    float v = si[(y0 + ry + ky) * SW + tx + kx];
                    #pragma unroll
                    for (int oc = 0; oc < OC; ++oc)
                        acc[ry][oc] = fmaf(v, wv[oc], acc[ry][oc]);
                }
            }
        }
    }

    // ---- write out ----
    float* outb = out + (size_t)n * OC * PLANE;
    #pragma unroll
    for (int ry = 0; ry < RY; ++ry) {
        int gy = gy0 + y0 + ry;
        #pragma unroll
        for (int oc = 0; oc < OC; ++oc) {
            float v = acc[ry][oc];
            if (RELU) v = fmaxf(v, 0.0f);
            outb[oc * PLANE + (gy << 9) + gx0 + tx] = v;
        }
    }
}

extern "C" void kernel_launch(void* const* d_in, const int* in_sizes, int n_in,
                              void* d_out, int out_size)
{
    const float* x    = (const float*)d_in[0];  // [8,1,512,512]
    const float* w1   = (const float*)d_in[1];  // [8,1,3,3]
    const float* wmid = (const float*)d_in[2];  // [18,8,8,3,3]
    const float* w20  = (const float*)d_in[3];  // [1,8,3,3]
    float* out = (float*)d_out;                 // [8,1,512,512]

    float* bufA = nullptr;
    float* bufB = nullptr;
    cudaGetSymbolAddress((void**)&bufA, g_bufA);
    cudaGetSymbolAddress((void**)&bufB, g_bufB);

    dim3 block(32, 8);
    dim3 grid(W / 32, H / 32, NB);

    // conv1: 1 -> 8, relu
    conv3x3_kernel<1, 8, true><<<grid, block>>>(x, w1, bufA);

    // conv2..19: 18x 8 -> 8, relu
    float* src = bufA;
    float* dst = bufB;
    for (int l = 0; l < 18; ++l) {
        conv3x3_kernel<8, 8, true><<<grid, block>>>(src, wmid + (size_t)l * 8 * 8 * 9, dst);
        float* t = src; src = dst; dst = t;
    }

    // conv20: 8 -> 1, no relu
    conv3x3_kernel<8, 1, false><<<grid, block>>>(src, w20, out);
}